// round 6
// baseline (speedup 1.0000x reference)
#include <cuda_runtime.h>

// ---------------------------------------------------------------------------
// QuantumBranch R5: R4 design with the constant-upload bug fixed
// (cudaGetSymbolAddress for the real device address of g_CONST).
//   z_w - z_0 = sum_{m,n} D'_w[m][n] * PP9[m] * QQ9[n], PP9/QQ9 = 9-monomial
//   vectors (c^2, cs, s^2 per qubit, Kronecker per pair). D' and the variance
//   quadform M''' live in __constant__ -> LDC/uniform path (no L1 beats).
//   Epilogue: lane owns 4 output dims, half-warps serve 2 elements/iter,
//   dup-packed qi in 4KB shared, f32x2 FMAs, coalesced STG.128.
// ---------------------------------------------------------------------------

typedef unsigned long long u64;

__device__    float g_CONST[260];       // [0..243): D'1,D'2,D'3 (81 each); [243..259): M'''
__constant__  float cCONST[260];
__device__    float4 g_epi4[16][6];     // per dim-quad: 8 WA, 8 WB, 4 beta, pad

__device__ __forceinline__ u64 pk2(float a, float b) {
    u64 r; asm("mov.b64 %0,{%1,%2};" : "=l"(r) : "f"(a), "f"(b)); return r;
}
__device__ __forceinline__ u64 f2fma(u64 a, u64 b, u64 c) {
    u64 d; asm("fma.rn.f32x2 %0,%1,%2,%3;" : "=l"(d) : "l"(a), "l"(b), "l"(c)); return d;
}

__device__ __forceinline__ float wsum(float v) {
    #pragma unroll
    for (int o = 16; o; o >>= 1) v += __shfl_xor_sync(0xffffffffu, v, o);
    return v;
}

__global__ void setup_kernel(const float* __restrict__ wts,
                             const float* __restrict__ W,
                             const float* __restrict__ b,
                             const float* __restrict__ gm,
                             const float* __restrict__ bt)
{
    __shared__ float2 sv[16][16];   // [col j][row k] = V[k][j]
    int tid = threadIdx.x;

    // ---- warp0 lanes 0..15: build V column j = tid (phases folded) ----
    if (tid < 16) {
        int j = tid;
        float2 st[16];
        #pragma unroll
        for (int k = 0; k < 16; k++) st[k] = make_float2(k == j ? 1.f : 0.f, 0.f);

        #pragma unroll
        for (int l = 0; l < 2; l++) {
            #pragma unroll
            for (int w = 0; w < 4; w++) {
                const float* g = wts + (l * 4 + w) * 3;
                float phi = g[0], th = g[1], om = g[2];
                float a = 0.5f * (phi + om), bb = 0.5f * (phi - om), hh = 0.5f * th;
                float sa, ca, sb, cb, stt, ct;
                __sincosf(a, &sa, &ca);
                __sincosf(bb, &sb, &cb);
                __sincosf(hh, &stt, &ct);
                float2 g00 = make_float2( ca * ct, -sa * ct);
                float2 g01 = make_float2(-cb * stt, -sb * stt);
                float2 g10 = make_float2( cb * stt, -sb * stt);
                float2 g11 = make_float2( ca * ct,  sa * ct);
                int mask = 8 >> w;
                #pragma unroll
                for (int k = 0; k < 16; k++) {
                    if (!(k & mask)) {
                        int k1 = k | mask;
                        float2 A = st[k], Bv = st[k1];
                        float2 t0, t1;
                        t0.x = g00.x * A.x - g00.y * A.y + g01.x * Bv.x - g01.y * Bv.y;
                        t0.y = g00.x * A.y + g00.y * A.x + g01.x * Bv.y + g01.y * Bv.x;
                        t1.x = g10.x * A.x - g10.y * A.y + g11.x * Bv.x - g11.y * Bv.y;
                        t1.y = g10.x * A.y + g10.y * A.x + g11.x * Bv.y + g11.y * Bv.x;
                        st[k] = t0; st[k1] = t1;
                    }
                }
            }
            int r = (l == 0) ? 1 : 2;
            #pragma unroll
            for (int w = 0; w < 4; w++) {
                int mc = 8 >> w, mt = 8 >> ((w + r) & 3);
                #pragma unroll
                for (int k = 0; k < 16; k++) {
                    if ((k & mc) && !(k & mt)) {
                        float2 tmp = st[k]; st[k] = st[k | mt]; st[k | mt] = tmp;
                    }
                }
            }
        }
        int pop = __popc(j) & 3;
        #pragma unroll
        for (int k = 0; k < 16; k++) {
            float2 v = st[k], o;
            if      (pop == 0) o = v;
            else if (pop == 1) o = make_float2( v.y, -v.x);
            else if (pop == 2) o = make_float2(-v.x, -v.y);
            else               o = make_float2(-v.y,  v.x);
            sv[j][k] = o;
        }
    }

    // ---- warp1: LayerNorm folds -> M''' and per-dim-quad epilogue consts ----
    if (tid >= 32) {
        int lane = tid - 32;
        const float inv64 = 1.f / 64.f;
        float wa[4], wb[4];
        #pragma unroll
        for (int i = 0; i < 4; i++) { wa[i] = W[lane * 4 + i]; wb[i] = W[(lane + 32) * 4 + i]; }
        float ba = b[lane], bbv = b[lane + 32];

        float cm[4];
        #pragma unroll
        for (int i = 0; i < 4; i++) cm[i] = wsum(wa[i] + wb[i]) * inv64;
        float bm = wsum(ba + bbv) * inv64;
        #pragma unroll
        for (int i = 0; i < 4; i++) { wa[i] -= cm[i]; wb[i] -= cm[i]; }
        ba -= bm; bbv -= bm;

        float M[4][4];
        #pragma unroll
        for (int i = 0; i < 4; i++) {
            #pragma unroll
            for (int k = 0; k < 4; k++) {
                if (k >= i) {
                    float v = wsum(wa[i] * wa[k] + wb[i] * wb[k]) * inv64;
                    M[i][k] = v; M[k][i] = v;
                }
            }
        }
        float vv[4];
        #pragma unroll
        for (int i = 0; i < 4; i++) vv[i] = wsum(wa[i] * ba + wb[i] * bbv) * (2.f * inv64);
        float vc = wsum(ba * ba + bbv * bbv) * inv64;

        if (lane == 0) {
            #pragma unroll
            for (int i = 0; i < 4; i++) {
                #pragma unroll
                for (int k = 0; k < 4; k++)
                    g_CONST[243 + i * 4 + k] =
                        M[i][k] + 0.5f * (vv[i] + vv[k]) + vc + 1e-5f;
            }
        }

        float ga = gm[lane], gb = gm[lane + 32];
        float bea = bt[lane], beb = bt[lane + 32];
        // dim d -> quad dq=d>>2, r=d&3; slots: r<2 -> [2k+r], r>=2 -> [8+2k+(r-2)], beta [16+r]
        {
            int d = lane, dq = d >> 2, r = d & 3;
            float* ep = (float*)&g_epi4[dq][0];
            int base = (r < 2) ? r : (8 + (r - 2));
            ep[base + 0] = (wa[0] + ba) * ga;
            ep[base + 2] = (wa[1] + ba) * ga;
            ep[base + 4] = (wa[2] + ba) * ga;
            ep[base + 6] = (wa[3] + ba) * ga;
            ep[16 + r]   = bea;
        }
        {
            int d = lane + 32, dq = d >> 2, r = d & 3;
            float* ep = (float*)&g_epi4[dq][0];
            int base = (r < 2) ? r : (8 + (r - 2));
            ep[base + 0] = (wb[0] + bbv) * gb;
            ep[base + 2] = (wb[1] + bbv) * gb;
            ep[base + 4] = (wb[2] + bbv) * gb;
            ep[base + 6] = (wb[3] + bbv) * gb;
            ep[16 + r]   = beb;
        }
    }

    __syncthreads();

    // ---- D'_w[m9][n9] = sum_{i,j} (A_w - A_0)[i][j] restricted to monomial (m9,n9)
    //      A_w[i][j] = sum_k sigma_w(k) Re(conj(V[k][i]) V[k][j]); qubit q <-> bit (3-q)
    for (int idx = tid; idx < 243; idx += 64) {
        int w = idx / 81 + 1;      // 1..3
        int mn = idx % 81;
        int m9 = mn / 9, n9 = mn % 9;
        int shift = 3 - w;
        float acc = 0.f;
        for (int i = 0; i < 16; i++) {
            for (int j = 0; j < 16; j++) {
                int mm = 3 * ((i >> 3) + (j >> 3)) + (((i >> 2) & 1) + ((j >> 2) & 1));
                int nn = 3 * (((i >> 1) & 1) + ((j >> 1) & 1)) + ((i & 1) + (j & 1));
                if (mm != m9 || nn != n9) continue;
                for (int k = 0; k < 16; k++) {
                    float rr = sv[i][k].x * sv[j][k].x + sv[i][k].y * sv[j][k].y;
                    float sw = ((k >> shift) & 1) ? -1.f : 1.f;
                    float s0 = (k & 8) ? -1.f : 1.f;
                    acc += (sw - s0) * rr;
                }
            }
        }
        g_CONST[idx] = acc;
    }
}

__global__ __launch_bounds__(128, 8) void qmain(const float4* __restrict__ x4,
                                                ulonglong2* __restrict__ out2)
{
    __shared__ ulonglong2 sQd[128][2];   // per element: {qi0,qi0},{qi1,qi1} / {qi2..},{qi3..}

    int tid = threadIdx.x;
    int lane = tid & 31, w = tid >> 5;
    int dq = lane & 15, half = lane >> 4;

    // epilogue constants for this lane's dim quad (5x LDG.128, pairs pre-adjacent)
    const ulonglong2* ec2 = (const ulonglong2*)&g_epi4[dq][0];
    ulonglong2 EA = ec2[0], EB = ec2[1], EC = ec2[2], ED = ec2[3], EE = ec2[4];
    u64 WA0 = EA.x, WA1 = EA.y, WA2 = EB.x, WA3 = EB.y;
    u64 WB0 = EC.x, WB1 = EC.y, WB2 = ED.x, WB3 = ED.y;
    u64 B01 = EE.x, B23 = EE.y;

    int gid = blockIdx.x * 128 + tid;
    float4 xv = x4[gid];

    // tanh via exp, half-angle sincos
    float cc[4], ss[4];
    {
        float xs[4] = {xv.x, xv.y, xv.z, xv.w};
        #pragma unroll
        for (int q = 0; q < 4; q++) {
            float e  = __expf(2.f * xs[q]);
            float th = __fdividef(e - 1.f, e + 1.f);
            __sincosf(th * 1.5707963267948966f, &ss[q], &cc[q]);
        }
    }

    // monomial 9-vectors: u = (c^2, c*s, s^2) per qubit; PP9 = u0 (x) u1, QQ9 = u2 (x) u3
    float U0[3] = {cc[0]*cc[0], cc[0]*ss[0], ss[0]*ss[0]};
    float U1[3] = {cc[1]*cc[1], cc[1]*ss[1], ss[1]*ss[1]};
    float U2[3] = {cc[2]*cc[2], cc[2]*ss[2], ss[2]*ss[2]};
    float U3[3] = {cc[3]*cc[3], cc[3]*ss[3], ss[3]*ss[3]};
    float PP[9], QQ[9];
    #pragma unroll
    for (int a = 0; a < 3; a++)
        #pragma unroll
        for (int c = 0; c < 3; c++) {
            PP[3*a + c] = U0[a] * U1[c];
            QQ[3*a + c] = U2[a] * U3[c];
        }

    // z-differences via constant-bank quadform (LDC/uniform path, no L1)
    float z1 = 0.f, z2 = 0.f, z3 = 0.f;
    #pragma unroll
    for (int m = 0; m < 9; m++) {
        float T1 = cCONST[      m * 9] * QQ[0];
        float T2 = cCONST[ 81 + m * 9] * QQ[0];
        float T3 = cCONST[162 + m * 9] * QQ[0];
        #pragma unroll
        for (int n = 1; n < 9; n++) {
            T1 = fmaf(cCONST[      m * 9 + n], QQ[n], T1);
            T2 = fmaf(cCONST[ 81 + m * 9 + n], QQ[n], T2);
            T3 = fmaf(cCONST[162 + m * 9 + n], QQ[n], T3);
        }
        z1 = fmaf(PP[m], T1, z1);
        z2 = fmaf(PP[m], T2, z2);
        z3 = fmaf(PP[m], T3, z3);
    }

    // softmax numerators with e0 = 1 (shift-invariant); qi = e * rsqrt(e^T M''' e)
    float e1 = __expf(z1), e2 = __expf(z2), e3 = __expf(z3);
    float t0 = fmaf(cCONST[244], e1, cCONST[243]);
    t0 = fmaf(cCONST[245], e2, t0); t0 = fmaf(cCONST[246], e3, t0);
    float t1 = fmaf(cCONST[248], e1, cCONST[247]);
    t1 = fmaf(cCONST[249], e2, t1); t1 = fmaf(cCONST[250], e3, t1);
    float t2 = fmaf(cCONST[252], e1, cCONST[251]);
    t2 = fmaf(cCONST[253], e2, t2); t2 = fmaf(cCONST[254], e3, t2);
    float t3 = fmaf(cCONST[256], e1, cCONST[255]);
    t3 = fmaf(cCONST[257], e2, t3); t3 = fmaf(cCONST[258], e3, t3);
    float uu = fmaf(e1, t1, t0);
    uu = fmaf(e2, t2, uu);
    uu = fmaf(e3, t3, uu);
    float rr = rsqrtf(uu);
    float qi0 = rr, qi1 = e1 * rr, qi2 = e2 * rr, qi3 = e3 * rr;

    sQd[tid][0] = make_ulonglong2(pk2(qi0, qi0), pk2(qi1, qi1));
    sQd[tid][1] = make_ulonglong2(pk2(qi2, qi2), pk2(qi3, qi3));
    __syncwarp();

    // epilogue: lane owns dims [4dq, 4dq+4); half-warps serve elements 2it / 2it+1
    size_t ebase = (size_t)blockIdx.x * 128 + (size_t)w * 32 + half;
    #pragma unroll
    for (int it = 0; it < 16; it++) {
        int el = w * 32 + 2 * it + half;
        ulonglong2 qa = sQd[el][0];
        ulonglong2 qb = sQd[el][1];
        u64 o01 = f2fma(WA0, qa.x, B01);
        o01 = f2fma(WA1, qa.y, o01);
        o01 = f2fma(WA2, qb.x, o01);
        o01 = f2fma(WA3, qb.y, o01);
        u64 o23 = f2fma(WB0, qa.x, B23);
        o23 = f2fma(WB1, qa.y, o23);
        o23 = f2fma(WB2, qb.x, o23);
        o23 = f2fma(WB3, qb.y, o23);
        out2[(ebase + 2 * it) * 16 + dq] = make_ulonglong2(o01, o23);
    }
}

extern "C" void kernel_launch(void* const* d_in, const int* in_sizes, int n_in,
                              void* d_out, int out_size)
{
    const float* x   = (const float*)d_in[0];
    const float* wts = (const float*)d_in[1];
    const float* W   = (const float*)d_in[2];
    const float* b   = (const float*)d_in[3];
    const float* gm  = (const float*)d_in[4];
    const float* bt  = (const float*)d_in[5];
    int B = in_sizes[0] / 4;

    setup_kernel<<<1, 64>>>(wts, W, b, gm, bt);

    // Resolve the REAL device address of g_CONST (the bare symbol name in host
    // code is the host shadow -- that was the R4 NaN bug), then D2D-copy into
    // the constant bank. Both calls are graph-capture-safe.
    void* src = nullptr;
    cudaGetSymbolAddress(&src, g_CONST);
    cudaMemcpyToSymbolAsync(cCONST, src, 260 * sizeof(float), 0,
                            cudaMemcpyDeviceToDevice);

    qmain<<<B / 128, 128>>>((const float4*)x, (ulonglong2*)d_out);
}

// round 8
// speedup vs baseline: 1.6728x; 1.6728x over previous
#include <cuda_runtime.h>

// ---------------------------------------------------------------------------
// QuantumBranch R6: global-memory broadcast-LDG constants (no __constant__,
// no memcpy node -- the R5 155us const-bank-patch overhead is gone).
//   z_w - z_0 = PP9^T D'_w QQ9 per element; D'1/D'2 pre-interleaved as float2
//   (loaded as 64-bit for f32x2), D'3 scalar + cross-element packing.
//   2 elements per thread: constant stream amortized 2x.
//   Epilogue: warp-local transpose through 4KB shared, coalesced STG.128.
// ---------------------------------------------------------------------------

typedef unsigned long long u64;

__device__ float2 g_D12[81];    // [m*9+n] = {D'1, D'2}
__device__ float  g_D3[84];     // [m*9+n] = D'3 (padded)
__device__ float4 g_M4[4];      // M''' rows (variance quadform, eps folded)
__device__ float4 g_epi4[16][6];// per dim-quad: 8 WA, 8 WB, 4 beta, pad

__device__ __forceinline__ u64 pk2(float a, float b) {
    u64 r; asm("mov.b64 %0,{%1,%2};" : "=l"(r) : "f"(a), "f"(b)); return r;
}
__device__ __forceinline__ void upk2(u64 v, float& a, float& b) {
    asm("mov.b64 {%0,%1},%2;" : "=f"(a), "=f"(b) : "l"(v));
}
__device__ __forceinline__ u64 f2fma(u64 a, u64 b, u64 c) {
    u64 d; asm("fma.rn.f32x2 %0,%1,%2,%3;" : "=l"(d) : "l"(a), "l"(b), "l"(c)); return d;
}
__device__ __forceinline__ u64 f2mul(u64 a, u64 b) {
    u64 d; asm("mul.rn.f32x2 %0,%1,%2;" : "=l"(d) : "l"(a), "l"(b)); return d;
}

__device__ __forceinline__ float wsum(float v) {
    #pragma unroll
    for (int o = 16; o; o >>= 1) v += __shfl_xor_sync(0xffffffffu, v, o);
    return v;
}

__global__ void setup_kernel(const float* __restrict__ wts,
                             const float* __restrict__ W,
                             const float* __restrict__ b,
                             const float* __restrict__ gm,
                             const float* __restrict__ bt)
{
    __shared__ float2 sv[16][16];   // [col j][row k] = V[k][j]
    int tid = threadIdx.x;

    // ---- warp0 lanes 0..15: build V column j = tid (phases folded) ----
    if (tid < 16) {
        int j = tid;
        float2 st[16];
        #pragma unroll
        for (int k = 0; k < 16; k++) st[k] = make_float2(k == j ? 1.f : 0.f, 0.f);

        #pragma unroll
        for (int l = 0; l < 2; l++) {
            #pragma unroll
            for (int w = 0; w < 4; w++) {
                const float* g = wts + (l * 4 + w) * 3;
                float phi = g[0], th = g[1], om = g[2];
                float a = 0.5f * (phi + om), bb = 0.5f * (phi - om), hh = 0.5f * th;
                float sa, ca, sb, cb, stt, ct;
                __sincosf(a, &sa, &ca);
                __sincosf(bb, &sb, &cb);
                __sincosf(hh, &stt, &ct);
                float2 g00 = make_float2( ca * ct, -sa * ct);
                float2 g01 = make_float2(-cb * stt, -sb * stt);
                float2 g10 = make_float2( cb * stt, -sb * stt);
                float2 g11 = make_float2( ca * ct,  sa * ct);
                int mask = 8 >> w;
                #pragma unroll
                for (int k = 0; k < 16; k++) {
                    if (!(k & mask)) {
                        int k1 = k | mask;
                        float2 A = st[k], Bv = st[k1];
                        float2 t0, t1;
                        t0.x = g00.x * A.x - g00.y * A.y + g01.x * Bv.x - g01.y * Bv.y;
                        t0.y = g00.x * A.y + g00.y * A.x + g01.x * Bv.y + g01.y * Bv.x;
                        t1.x = g10.x * A.x - g10.y * A.y + g11.x * Bv.x - g11.y * Bv.y;
                        t1.y = g10.x * A.y + g10.y * A.x + g11.x * Bv.y + g11.y * Bv.x;
                        st[k] = t0; st[k1] = t1;
                    }
                }
            }
            int r = (l == 0) ? 1 : 2;
            #pragma unroll
            for (int w = 0; w < 4; w++) {
                int mc = 8 >> w, mt = 8 >> ((w + r) & 3);
                #pragma unroll
                for (int k = 0; k < 16; k++) {
                    if ((k & mc) && !(k & mt)) {
                        float2 tmp = st[k]; st[k] = st[k | mt]; st[k | mt] = tmp;
                    }
                }
            }
        }
        int pop = __popc(j) & 3;
        #pragma unroll
        for (int k = 0; k < 16; k++) {
            float2 v = st[k], o;
            if      (pop == 0) o = v;
            else if (pop == 1) o = make_float2( v.y, -v.x);
            else if (pop == 2) o = make_float2(-v.x, -v.y);
            else               o = make_float2(-v.y,  v.x);
            sv[j][k] = o;
        }
    }

    // ---- warp1 (tid 32..63): LayerNorm folds -> M''' + epilogue consts ----
    if (tid >= 32 && tid < 64) {
        int lane = tid - 32;
        const float inv64 = 1.f / 64.f;
        float wa[4], wb[4];
        #pragma unroll
        for (int i = 0; i < 4; i++) { wa[i] = W[lane * 4 + i]; wb[i] = W[(lane + 32) * 4 + i]; }
        float ba = b[lane], bbv = b[lane + 32];

        float cm[4];
        #pragma unroll
        for (int i = 0; i < 4; i++) cm[i] = wsum(wa[i] + wb[i]) * inv64;
        float bm = wsum(ba + bbv) * inv64;
        #pragma unroll
        for (int i = 0; i < 4; i++) { wa[i] -= cm[i]; wb[i] -= cm[i]; }
        ba -= bm; bbv -= bm;

        float M[4][4];
        #pragma unroll
        for (int i = 0; i < 4; i++) {
            #pragma unroll
            for (int k = 0; k < 4; k++) {
                if (k >= i) {
                    float v = wsum(wa[i] * wa[k] + wb[i] * wb[k]) * inv64;
                    M[i][k] = v; M[k][i] = v;
                }
            }
        }
        float vv[4];
        #pragma unroll
        for (int i = 0; i < 4; i++) vv[i] = wsum(wa[i] * ba + wb[i] * bbv) * (2.f * inv64);
        float vc = wsum(ba * ba + bbv * bbv) * inv64;

        if (lane == 0) {
            float* Mo = (float*)g_M4;
            #pragma unroll
            for (int i = 0; i < 4; i++)
                #pragma unroll
                for (int k = 0; k < 4; k++)
                    Mo[i * 4 + k] = M[i][k] + 0.5f * (vv[i] + vv[k]) + vc + 1e-5f;
        }

        float ga = gm[lane], gb = gm[lane + 32];
        float bea = bt[lane], beb = bt[lane + 32];
        {
            int d = lane, dq = d >> 2, r = d & 3;
            float* ep = (float*)&g_epi4[dq][0];
            int base = (r < 2) ? r : (8 + (r - 2));
            ep[base + 0] = (wa[0] + ba) * ga;
            ep[base + 2] = (wa[1] + ba) * ga;
            ep[base + 4] = (wa[2] + ba) * ga;
            ep[base + 6] = (wa[3] + ba) * ga;
            ep[16 + r]   = bea;
        }
        {
            int d = lane + 32, dq = d >> 2, r = d & 3;
            float* ep = (float*)&g_epi4[dq][0];
            int base = (r < 2) ? r : (8 + (r - 2));
            ep[base + 0] = (wb[0] + bbv) * gb;
            ep[base + 2] = (wb[1] + bbv) * gb;
            ep[base + 4] = (wb[2] + bbv) * gb;
            ep[base + 6] = (wb[3] + bbv) * gb;
            ep[16 + r]   = beb;
        }
    }

    __syncthreads();

    // ---- all 128 threads: D'_w[m9][n9] (same math as validated R5) ----
    for (int idx = tid; idx < 243; idx += 128) {
        int w = idx / 81 + 1;      // 1..3
        int mn = idx % 81;
        int m9 = mn / 9, n9 = mn % 9;
        int shift = 3 - w;
        float acc = 0.f;
        for (int i = 0; i < 16; i++) {
            for (int j = 0; j < 16; j++) {
                int mm = 3 * ((i >> 3) + (j >> 3)) + (((i >> 2) & 1) + ((j >> 2) & 1));
                int nn = 3 * (((i >> 1) & 1) + ((j >> 1) & 1)) + ((i & 1) + (j & 1));
                if (mm != m9 || nn != n9) continue;
                for (int k = 0; k < 16; k++) {
                    float rr = sv[i][k].x * sv[j][k].x + sv[i][k].y * sv[j][k].y;
                    float sw = ((k >> shift) & 1) ? -1.f : 1.f;
                    float s0 = (k & 8) ? -1.f : 1.f;
                    acc += (sw - s0) * rr;
                }
            }
        }
        if      (w == 1) g_D12[mn].x = acc;
        else if (w == 2) g_D12[mn].y = acc;
        else             g_D3[mn]    = acc;
    }
}

__global__ __launch_bounds__(128, 4) void qmain(const float4* __restrict__ x4,
                                                ulonglong2* __restrict__ out2)
{
    __shared__ float4 sQ[256];   // per element: {qi0, qi1, qi2, qi3}

    int tid = threadIdx.x;
    int l = tid & 31, w = tid >> 5;
    int dq = l & 15, half = l >> 4;

    const u64*   D12 = (const u64*)g_D12;
    const float* D3  = (const float*)g_D3;

    // two elements per thread, warp-local: eA = w*64+l, eB = eA+32 (block-rel)
    int ebA = w * 64 + l;
    int gbase = blockIdx.x * 256;
    float4 xA = x4[gbase + ebA];
    float4 xB = x4[gbase + ebA + 32];

    // tanh via exp, half-angle sincos (both elements)
    float ccA[4], ssA[4], ccB[4], ssB[4];
    {
        float xsA[4] = {xA.x, xA.y, xA.z, xA.w};
        float xsB[4] = {xB.x, xB.y, xB.z, xB.w};
        #pragma unroll
        for (int q = 0; q < 4; q++) {
            float eA = __expf(2.f * xsA[q]);
            float tA = __fdividef(eA - 1.f, eA + 1.f);
            __sincosf(tA * 1.5707963267948966f, &ssA[q], &ccA[q]);
            float eB = __expf(2.f * xsB[q]);
            float tB = __fdividef(eB - 1.f, eB + 1.f);
            __sincosf(tB * 1.5707963267948966f, &ssB[q], &ccB[q]);
        }
    }

    // monomial 9-vectors per element
    float PPA[9], PPB[9];
    u64 QQdA[9], QQdB[9], QQab[9];
    {
        float U0A[3] = {ccA[0]*ccA[0], ccA[0]*ssA[0], ssA[0]*ssA[0]};
        float U1A[3] = {ccA[1]*ccA[1], ccA[1]*ssA[1], ssA[1]*ssA[1]};
        float U2A[3] = {ccA[2]*ccA[2], ccA[2]*ssA[2], ssA[2]*ssA[2]};
        float U3A[3] = {ccA[3]*ccA[3], ccA[3]*ssA[3], ssA[3]*ssA[3]};
        float U0B[3] = {ccB[0]*ccB[0], ccB[0]*ssB[0], ssB[0]*ssB[0]};
        float U1B[3] = {ccB[1]*ccB[1], ccB[1]*ssB[1], ssB[1]*ssB[1]};
        float U2B[3] = {ccB[2]*ccB[2], ccB[2]*ssB[2], ssB[2]*ssB[2]};
        float U3B[3] = {ccB[3]*ccB[3], ccB[3]*ssB[3], ssB[3]*ssB[3]};
        #pragma unroll
        for (int a = 0; a < 3; a++)
            #pragma unroll
            for (int c = 0; c < 3; c++) {
                int i = 3*a + c;
                PPA[i] = U0A[a] * U1A[c];
                PPB[i] = U0B[a] * U1B[c];
                float qa = U2A[a] * U3A[c];
                float qb = U2B[a] * U3B[c];
                QQdA[i] = pk2(qa, qa);
                QQdB[i] = pk2(qb, qb);
                QQab[i] = pk2(qa, qb);
            }
    }

    // quadform: z12 per element (packed z1,z2), z3 cross-packed {z3A,z3B}
    u64 z12A, z12B, z3ab;
    #pragma unroll
    for (int m = 0; m < 9; m++) {
        u64 c12 = D12[m * 9];
        float c3 = D3[m * 9];
        u64 c3d = pk2(c3, c3);
        u64 T12A = f2mul(c12, QQdA[0]);
        u64 T12B = f2mul(c12, QQdB[0]);
        u64 T3   = f2mul(c3d, QQab[0]);
        #pragma unroll
        for (int n = 1; n < 9; n++) {
            u64 c12n = D12[m * 9 + n];
            float c3n = D3[m * 9 + n];
            u64 c3dn = pk2(c3n, c3n);
            T12A = f2fma(c12n, QQdA[n], T12A);
            T12B = f2fma(c12n, QQdB[n], T12B);
            T3   = f2fma(c3dn, QQab[n], T3);
        }
        u64 pA = pk2(PPA[m], PPA[m]);
        u64 pB = pk2(PPB[m], PPB[m]);
        u64 pab = pk2(PPA[m], PPB[m]);
        if (m == 0) {
            z12A = f2mul(pA, T12A);
            z12B = f2mul(pB, T12B);
            z3ab = f2mul(pab, T3);
        } else {
            z12A = f2fma(pA, T12A, z12A);
            z12B = f2fma(pB, T12B, z12B);
            z3ab = f2fma(pab, T3, z3ab);
        }
    }
    float z1A, z2A, z1B, z2B, z3A, z3B;
    upk2(z12A, z1A, z2A); upk2(z12B, z1B, z2B); upk2(z3ab, z3A, z3B);

    // softmax numerators (e0 = 1); qi = e * rsqrt(e^T M''' e)
    float e1A = __expf(z1A), e2A = __expf(z2A), e3A = __expf(z3A);
    float e1B = __expf(z1B), e2B = __expf(z2B), e3B = __expf(z3B);
    {
        float4 M0 = g_M4[0], M1 = g_M4[1], M2 = g_M4[2], M3 = g_M4[3];
        float t0 = fmaf(M0.y, e1A, M0.x); t0 = fmaf(M0.z, e2A, t0); t0 = fmaf(M0.w, e3A, t0);
        float t1 = fmaf(M1.y, e1A, M1.x); t1 = fmaf(M1.z, e2A, t1); t1 = fmaf(M1.w, e3A, t1);
        float t2 = fmaf(M2.y, e1A, M2.x); t2 = fmaf(M2.z, e2A, t2); t2 = fmaf(M2.w, e3A, t2);
        float t3 = fmaf(M3.y, e1A, M3.x); t3 = fmaf(M3.z, e2A, t3); t3 = fmaf(M3.w, e3A, t3);
        float uuA = fmaf(e1A, t1, t0); uuA = fmaf(e2A, t2, uuA); uuA = fmaf(e3A, t3, uuA);
        float rA = rsqrtf(uuA);
        sQ[ebA] = make_float4(rA, e1A * rA, e2A * rA, e3A * rA);

        float s0 = fmaf(M0.y, e1B, M0.x); s0 = fmaf(M0.z, e2B, s0); s0 = fmaf(M0.w, e3B, s0);
        float s1 = fmaf(M1.y, e1B, M1.x); s1 = fmaf(M1.z, e2B, s1); s1 = fmaf(M1.w, e3B, s1);
        float s2 = fmaf(M2.y, e1B, M2.x); s2 = fmaf(M2.z, e2B, s2); s2 = fmaf(M2.w, e3B, s2);
        float s3 = fmaf(M3.y, e1B, M3.x); s3 = fmaf(M3.z, e2B, s3); s3 = fmaf(M3.w, e3B, s3);
        float uuB = fmaf(e1B, s1, s0); uuB = fmaf(e2B, s2, uuB); uuB = fmaf(e3B, s3, uuB);
        float rB = rsqrtf(uuB);
        sQ[ebA + 32] = make_float4(rB, e1B * rB, e2B * rB, e3B * rB);
    }
    __syncwarp();

    // epilogue constants for this lane's dim quad (loaded late: short live range)
    const ulonglong2* ec2 = (const ulonglong2*)&g_epi4[dq][0];
    ulonglong2 EA = ec2[0], EB = ec2[1], EC = ec2[2], ED = ec2[3], EE = ec2[4];
    u64 WA0 = EA.x, WA1 = EA.y, WA2 = EB.x, WA3 = EB.y;
    u64 WB0 = EC.x, WB1 = EC.y, WB2 = ED.x, WB3 = ED.y;
    u64 B01 = EE.x, B23 = EE.y;

    // warp-local transpose epilogue: halves serve elements 2it / 2it+1
    #pragma unroll
    for (int it = 0; it < 32; it++) {
        int el = w * 64 + 2 * it + half;
        float4 q = sQ[el];
        u64 q0 = pk2(q.x, q.x), q1 = pk2(q.y, q.y);
        u64 q2 = pk2(q.z, q.z), q3 = pk2(q.w, q.w);
        u64 o01 = f2fma(WA0, q0, B01);
        o01 = f2fma(WA1, q1, o01);
        o01 = f2fma(WA2, q2, o01);
        o01 = f2fma(WA3, q3, o01);
        u64 o23 = f2fma(WB0, q0, B23);
        o23 = f2fma(WB1, q1, o23);
        o23 = f2fma(WB2, q2, o23);
        o23 = f2fma(WB3, q3, o23);
        out2[((size_t)gbase + el) * 16 + dq] = make_ulonglong2(o01, o23);
    }
}

extern "C" void kernel_launch(void* const* d_in, const int* in_sizes, int n_in,
                              void* d_out, int out_size)
{
    const float* x   = (const float*)d_in[0];
    const float* wts = (const float*)d_in[1];
    const float* W   = (const float*)d_in[2];
    const float* b   = (const float*)d_in[3];
    const float* gm  = (const float*)d_in[4];
    const float* bt  = (const float*)d_in[5];
    int B = in_sizes[0] / 4;

    setup_kernel<<<1, 128>>>(wts, W, b, gm, bt);
    qmain<<<B / 256, 128>>>((const float4*)x, (ulonglong2*)d_out);
}

// round 9
// speedup vs baseline: 5.3353x; 3.1895x over previous
#include <cuda_runtime.h>

// ---------------------------------------------------------------------------
// QuantumBranch R8: fast two-phase D' setup (~5us, was ~81us) + R5's proven
// constant-bank qmain (33.9us) + cheap memcpy-to-constant node (~3us).
//   z_w - z_0 = PP9^T D'_w QQ9 (9-monomial quadform, uniform/LDC datapath).
//   qi = e * rsqrt(e^T M''' e)  (softmax shift e0=1, sum(q)=1 folds).
//   Epilogue: lane owns 4 output dims, half-warps serve 2 elems/iter,
//   float4 qi staging (pk2 at use), coalesced 512B STG.128 bursts.
// ---------------------------------------------------------------------------

typedef unsigned long long u64;

__device__    float g_CONST[260];       // [0..243): D'1,D'2,D'3 (81 each); [243..259): M'''
__constant__  float cCONST[260];
__device__    float4 g_epi4[16][6];     // per dim-quad: 8 WA, 8 WB, 4 beta, pad

__device__ __forceinline__ u64 pk2(float a, float b) {
    u64 r; asm("mov.b64 %0,{%1,%2};" : "=l"(r) : "f"(a), "f"(b)); return r;
}
__device__ __forceinline__ u64 f2fma(u64 a, u64 b, u64 c) {
    u64 d; asm("fma.rn.f32x2 %0,%1,%2,%3;" : "=l"(d) : "l"(a), "l"(b), "l"(c)); return d;
}

__device__ __forceinline__ float wsum(float v) {
    #pragma unroll
    for (int o = 16; o; o >>= 1) v += __shfl_xor_sync(0xffffffffu, v, o);
    return v;
}

__global__ void setup_kernel(const float* __restrict__ wts,
                             const float* __restrict__ W,
                             const float* __restrict__ b,
                             const float* __restrict__ gm,
                             const float* __restrict__ bt)
{
    __shared__ float2 sv[16][16];    // [col j][row k] = V[k][j]
    __shared__ float  sG[3][256];    // per (i,j) pair: G_w[i][j]
    int tid = threadIdx.x;

    // ---- warp0 lanes 0..15: build V column j = tid (phases folded) ----
    if (tid < 16) {
        int j = tid;
        float2 st[16];
        #pragma unroll
        for (int k = 0; k < 16; k++) st[k] = make_float2(k == j ? 1.f : 0.f, 0.f);

        #pragma unroll
        for (int l = 0; l < 2; l++) {
            #pragma unroll
            for (int w = 0; w < 4; w++) {
                const float* g = wts + (l * 4 + w) * 3;
                float phi = g[0], th = g[1], om = g[2];
                float a = 0.5f * (phi + om), bb = 0.5f * (phi - om), hh = 0.5f * th;
                float sa, ca, sb, cb, stt, ct;
                __sincosf(a, &sa, &ca);
                __sincosf(bb, &sb, &cb);
                __sincosf(hh, &stt, &ct);
                float2 g00 = make_float2( ca * ct, -sa * ct);
                float2 g01 = make_float2(-cb * stt, -sb * stt);
                float2 g10 = make_float2( cb * stt, -sb * stt);
                float2 g11 = make_float2( ca * ct,  sa * ct);
                int mask = 8 >> w;
                #pragma unroll
                for (int k = 0; k < 16; k++) {
                    if (!(k & mask)) {
                        int k1 = k | mask;
                        float2 A = st[k], Bv = st[k1];
                        float2 t0, t1;
                        t0.x = g00.x * A.x - g00.y * A.y + g01.x * Bv.x - g01.y * Bv.y;
                        t0.y = g00.x * A.y + g00.y * A.x + g01.x * Bv.y + g01.y * Bv.x;
                        t1.x = g10.x * A.x - g10.y * A.y + g11.x * Bv.x - g11.y * Bv.y;
                        t1.y = g10.x * A.y + g10.y * A.x + g11.x * Bv.y + g11.y * Bv.x;
                        st[k] = t0; st[k1] = t1;
                    }
                }
            }
            int r = (l == 0) ? 1 : 2;
            #pragma unroll
            for (int w = 0; w < 4; w++) {
                int mc = 8 >> w, mt = 8 >> ((w + r) & 3);
                #pragma unroll
                for (int k = 0; k < 16; k++) {
                    if ((k & mc) && !(k & mt)) {
                        float2 tmp = st[k]; st[k] = st[k | mt]; st[k | mt] = tmp;
                    }
                }
            }
        }
        int pop = __popc(j) & 3;
        #pragma unroll
        for (int k = 0; k < 16; k++) {
            float2 v = st[k], o;
            if      (pop == 0) o = v;
            else if (pop == 1) o = make_float2( v.y, -v.x);
            else if (pop == 2) o = make_float2(-v.x, -v.y);
            else               o = make_float2(-v.y,  v.x);
            sv[j][k] = o;
        }
    }

    // ---- warp1 (tid 32..63): LayerNorm folds -> M''' + epilogue consts ----
    if (tid >= 32 && tid < 64) {
        int lane = tid - 32;
        const float inv64 = 1.f / 64.f;
        float wa[4], wb[4];
        #pragma unroll
        for (int i = 0; i < 4; i++) { wa[i] = W[lane * 4 + i]; wb[i] = W[(lane + 32) * 4 + i]; }
        float ba = b[lane], bbv = b[lane + 32];

        float cm[4];
        #pragma unroll
        for (int i = 0; i < 4; i++) cm[i] = wsum(wa[i] + wb[i]) * inv64;
        float bm = wsum(ba + bbv) * inv64;
        #pragma unroll
        for (int i = 0; i < 4; i++) { wa[i] -= cm[i]; wb[i] -= cm[i]; }
        ba -= bm; bbv -= bm;

        float M[4][4];
        #pragma unroll
        for (int i = 0; i < 4; i++) {
            #pragma unroll
            for (int k = 0; k < 4; k++) {
                if (k >= i) {
                    float v = wsum(wa[i] * wa[k] + wb[i] * wb[k]) * inv64;
                    M[i][k] = v; M[k][i] = v;
                }
            }
        }
        float vv[4];
        #pragma unroll
        for (int i = 0; i < 4; i++) vv[i] = wsum(wa[i] * ba + wb[i] * bbv) * (2.f * inv64);
        float vc = wsum(ba * ba + bbv * bbv) * inv64;

        if (lane == 0) {
            #pragma unroll
            for (int i = 0; i < 4; i++)
                #pragma unroll
                for (int k = 0; k < 4; k++)
                    g_CONST[243 + i * 4 + k] =
                        M[i][k] + 0.5f * (vv[i] + vv[k]) + vc + 1e-5f;
        }

        float ga = gm[lane], gb = gm[lane + 32];
        float bea = bt[lane], beb = bt[lane + 32];
        {
            int d = lane, dq = d >> 2, r = d & 3;
            float* ep = (float*)&g_epi4[dq][0];
            int base = (r < 2) ? r : (8 + (r - 2));
            ep[base + 0] = (wa[0] + ba) * ga;
            ep[base + 2] = (wa[1] + ba) * ga;
            ep[base + 4] = (wa[2] + ba) * ga;
            ep[base + 6] = (wa[3] + ba) * ga;
            ep[16 + r]   = bea;
        }
        {
            int d = lane + 32, dq = d >> 2, r = d & 3;
            float* ep = (float*)&g_epi4[dq][0];
            int base = (r < 2) ? r : (8 + (r - 2));
            ep[base + 0] = (wb[0] + bbv) * gb;
            ep[base + 2] = (wb[1] + bbv) * gb;
            ep[base + 4] = (wb[2] + bbv) * gb;
            ep[base + 6] = (wb[3] + bbv) * gb;
            ep[16 + r]   = beb;
        }
    }

    __syncthreads();

    // ---- Phase A: per (i,j) pair, G_w[i][j] = sum_k (sigma_w - sigma_0) Re(V*_i V_j)
    {
        int i = tid >> 4, j = tid & 15;
        float g1 = 0.f, g2 = 0.f, g3 = 0.f;
        #pragma unroll
        for (int k = 0; k < 16; k++) {
            float rr = sv[i][k].x * sv[j][k].x + sv[i][k].y * sv[j][k].y;
            float s0 = (k & 8) ? -1.f : 1.f;
            g1 += (((k & 4) ? -1.f : 1.f) - s0) * rr;
            g2 += (((k & 2) ? -1.f : 1.f) - s0) * rr;
            g3 += (((k & 1) ? -1.f : 1.f) - s0) * rr;
        }
        sG[0][tid] = g1; sG[1][tid] = g2; sG[2][tid] = g3;
    }
    __syncthreads();

    // ---- Phase B: D'_w[m9][n9] = sum over matching (hi,lo) pairs of G ----
    if (tid < 243) {
        int w = tid / 81;          // 0..2 -> D'1..D'3
        int mn = tid % 81;
        int m9 = mn / 9, n9 = mn % 9;
        float acc = 0.f;
        #pragma unroll
        for (int ha = 0; ha < 4; ha++)
            #pragma unroll
            for (int hb = 0; hb < 4; hb++) {
                int mm = 3 * ((ha >> 1) + (hb >> 1)) + ((ha & 1) + (hb & 1));
                if (mm != m9) continue;
                #pragma unroll
                for (int la = 0; la < 4; la++)
                    #pragma unroll
                    for (int lb = 0; lb < 4; lb++) {
                        int nn = 3 * ((la >> 1) + (lb >> 1)) + ((la & 1) + (lb & 1));
                        if (nn != n9) continue;
                        acc += sG[w][(4 * ha + la) * 16 + (4 * hb + lb)];
                    }
            }
        g_CONST[tid] = acc;
    }
}

__global__ __launch_bounds__(128, 8) void qmain(const float4* __restrict__ x4,
                                                ulonglong2* __restrict__ out2)
{
    __shared__ float4 sQ[128];   // per element: {qi0, qi1, qi2, qi3}

    int tid = threadIdx.x;
    int lane = tid & 31, w = tid >> 5;
    int dq = lane & 15, half = lane >> 4;

    int gid = blockIdx.x * 128 + tid;
    float4 xv = x4[gid];

    // tanh via exp, half-angle sincos
    float cc[4], ss[4];
    {
        float xs[4] = {xv.x, xv.y, xv.z, xv.w};
        #pragma unroll
        for (int q = 0; q < 4; q++) {
            float e  = __expf(2.f * xs[q]);
            float th = __fdividef(e - 1.f, e + 1.f);
            __sincosf(th * 1.5707963267948966f, &ss[q], &cc[q]);
        }
    }

    // monomial 9-vectors: u = (c^2, c*s, s^2) per qubit; PP9 = u0 (x) u1, QQ9 = u2 (x) u3
    float U0[3] = {cc[0]*cc[0], cc[0]*ss[0], ss[0]*ss[0]};
    float U1[3] = {cc[1]*cc[1], cc[1]*ss[1], ss[1]*ss[1]};
    float U2[3] = {cc[2]*cc[2], cc[2]*ss[2], ss[2]*ss[2]};
    float U3[3] = {cc[3]*cc[3], cc[3]*ss[3], ss[3]*ss[3]};
    float PP[9], QQ[9];
    #pragma unroll
    for (int a = 0; a < 3; a++)
        #pragma unroll
        for (int c = 0; c < 3; c++) {
            PP[3*a + c] = U0[a] * U1[c];
            QQ[3*a + c] = U2[a] * U3[c];
        }

    // z-differences via constant-bank quadform (uniform datapath, no L1)
    float z1 = 0.f, z2 = 0.f, z3 = 0.f;
    #pragma unroll
    for (int m = 0; m < 9; m++) {
        float T1 = cCONST[      m * 9] * QQ[0];
        float T2 = cCONST[ 81 + m * 9] * QQ[0];
        float T3 = cCONST[162 + m * 9] * QQ[0];
        #pragma unroll
        for (int n = 1; n < 9; n++) {
            T1 = fmaf(cCONST[      m * 9 + n], QQ[n], T1);
            T2 = fmaf(cCONST[ 81 + m * 9 + n], QQ[n], T2);
            T3 = fmaf(cCONST[162 + m * 9 + n], QQ[n], T3);
        }
        z1 = fmaf(PP[m], T1, z1);
        z2 = fmaf(PP[m], T2, z2);
        z3 = fmaf(PP[m], T3, z3);
    }

    // softmax numerators with e0 = 1 (shift-invariant); qi = e * rsqrt(e^T M''' e)
    float e1 = __expf(z1), e2 = __expf(z2), e3 = __expf(z3);
    float t0 = fmaf(cCONST[244], e1, cCONST[243]);
    t0 = fmaf(cCONST[245], e2, t0); t0 = fmaf(cCONST[246], e3, t0);
    float t1 = fmaf(cCONST[248], e1, cCONST[247]);
    t1 = fmaf(cCONST[249], e2, t1); t1 = fmaf(cCONST[250], e3, t1);
    float t2 = fmaf(cCONST[252], e1, cCONST[251]);
    t2 = fmaf(cCONST[253], e2, t2); t2 = fmaf(cCONST[254], e3, t2);
    float t3 = fmaf(cCONST[256], e1, cCONST[255]);
    t3 = fmaf(cCONST[257], e2, t3); t3 = fmaf(cCONST[258], e3, t3);
    float uu = fmaf(e1, t1, t0);
    uu = fmaf(e2, t2, uu);
    uu = fmaf(e3, t3, uu);
    float rr = rsqrtf(uu);

    sQ[tid] = make_float4(rr, e1 * rr, e2 * rr, e3 * rr);
    __syncwarp();

    // epilogue constants for this lane's dim quad (late load, short live range)
    const ulonglong2* ec2 = (const ulonglong2*)&g_epi4[dq][0];
    ulonglong2 EA = ec2[0], EB = ec2[1], EC = ec2[2], ED = ec2[3], EE = ec2[4];
    u64 WA0 = EA.x, WA1 = EA.y, WA2 = EB.x, WA3 = EB.y;
    u64 WB0 = EC.x, WB1 = EC.y, WB2 = ED.x, WB3 = ED.y;
    u64 B01 = EE.x, B23 = EE.y;

    // epilogue: lane owns dims [4dq, 4dq+4); half-warps serve elements 2it / 2it+1
    size_t ebase = (size_t)blockIdx.x * 128 + (size_t)w * 32 + half;
    #pragma unroll
    for (int it = 0; it < 16; it++) {
        int el = w * 32 + 2 * it + half;
        float4 q = sQ[el];
        u64 q0 = pk2(q.x, q.x), q1 = pk2(q.y, q.y);
        u64 q2 = pk2(q.z, q.z), q3 = pk2(q.w, q.w);
        u64 o01 = f2fma(WA0, q0, B01);
        o01 = f2fma(WA1, q1, o01);
        o01 = f2fma(WA2, q2, o01);
        o01 = f2fma(WA3, q3, o01);
        u64 o23 = f2fma(WB0, q0, B23);
        o23 = f2fma(WB1, q1, o23);
        o23 = f2fma(WB2, q2, o23);
        o23 = f2fma(WB3, q3, o23);
        out2[(ebase + 2 * it) * 16 + dq] = make_ulonglong2(o01, o23);
    }
}

extern "C" void kernel_launch(void* const* d_in, const int* in_sizes, int n_in,
                              void* d_out, int out_size)
{
    const float* x   = (const float*)d_in[0];
    const float* wts = (const float*)d_in[1];
    const float* W   = (const float*)d_in[2];
    const float* b   = (const float*)d_in[3];
    const float* gm  = (const float*)d_in[4];
    const float* bt  = (const float*)d_in[5];
    int B = in_sizes[0] / 4;

    setup_kernel<<<1, 256>>>(wts, W, b, gm, bt);

    void* src = nullptr;
    cudaGetSymbolAddress(&src, g_CONST);
    cudaMemcpyToSymbolAsync(cCONST, src, 260 * sizeof(float), 0,
                            cudaMemcpyDeviceToDevice);

    qmain<<<B / 128, 128>>>((const float4*)x, (ulonglong2*)d_out);
}